// round 2
// baseline (speedup 1.0000x reference)
#include <cuda_runtime.h>
#include <cstdint>

#define NC 19
#define NB 16
#define HWS (512*512)
#define NPIX (NB*HWS)                 // 4,194,304 pixels
#define EPSF 1e-8f
#define THREADS 256
#define NBLOCKS (NPIX/THREADS)        // 16384
#define RED_THREADS 1024

// Precomputed confusion-matrix softmax tables
__device__ float g_ncm[NC*NC];
__device__ float g_logncm[NC*NC];
__device__ float g_partial[NBLOCKS];

// ---------------------------------------------------------------------------
// Kernel 0: row-softmax of 19x19 confusion matrix + log table. Trivial cost.
// ---------------------------------------------------------------------------
__global__ void prep_kernel(const float* __restrict__ cm) {
    int r = threadIdx.x;
    if (r < NC) {
        float row[NC];
        float m = -1e30f;
        #pragma unroll
        for (int j = 0; j < NC; j++) { row[j] = cm[r*NC + j]; m = fmaxf(m, row[j]); }
        float s = 0.f;
        #pragma unroll
        for (int j = 0; j < NC; j++) { row[j] = expf(row[j] - m); s += row[j]; }
        float inv = 1.f / s;
        #pragma unroll
        for (int j = 0; j < NC; j++) {
            float v = row[j] * inv;
            g_ncm[r*NC + j]    = v;
            g_logncm[r*NC + j] = logf(v + EPSF);
        }
    }
}

// ---------------------------------------------------------------------------
// Kernel 1: per-pixel softmax + EM loss, block-partial reduction (deterministic)
// ---------------------------------------------------------------------------
__global__ void __launch_bounds__(THREADS)
emloss_main(const float* __restrict__ logits,
            const int* __restrict__ targets,
            float* __restrict__ pred_out) {
    __shared__ float s_ncm[NC*NC];
    __shared__ float s_log[NC*NC];
    for (int i = threadIdx.x; i < NC*NC; i += THREADS) {
        s_ncm[i] = g_ncm[i];
        s_log[i] = g_logncm[i];
    }
    __syncthreads();

    const int p  = blockIdx.x * THREADS + threadIdx.x;   // pixel index
    const int b  = p / HWS;
    const int hw = p - b * HWS;
    const size_t base = (size_t)b * NC * HWS + hw;

    // Load all 19 class logits (coalesced per warp, MLP=19)
    float x[NC];
    #pragma unroll
    for (int c = 0; c < NC; c++)
        x[c] = __ldg(logits + base + (size_t)c * HWS);

    // Stable softmax over classes
    float m = x[0];
    #pragma unroll
    for (int c = 1; c < NC; c++) m = fmaxf(m, x[c]);
    float s = 0.f;
    #pragma unroll
    for (int c = 0; c < NC; c++) { x[c] = __expf(x[c] - m); s += x[c]; }
    const float inv = 1.f / s;

    const int t = targets[p];

    // pred store + numel sum
    float ns = 0.f;
    #pragma unroll
    for (int c = 0; c < NC; c++) {
        float pv = x[c] * inv;
        x[c] = pv;
        pred_out[base + (size_t)c * HWS] = pv;
        ns += s_ncm[c*NC + t] * pv;
    }
    const float invns = 1.f / ns;

    // loss = sum_c q_c * (log(ncm[c,t]+eps) + log(pred_c+eps))
    float loss = 0.f;
    #pragma unroll
    for (int c = 0; c < NC; c++) {
        float q = s_ncm[c*NC + t] * x[c] * invns;
        loss += q * (s_log[c*NC + t] + __logf(x[c] + EPSF));
    }

    // Deterministic block reduction: warp shuffle then shared tree
    #pragma unroll
    for (int off = 16; off > 0; off >>= 1)
        loss += __shfl_down_sync(0xffffffffu, loss, off);

    __shared__ float s_red[THREADS/32];
    if ((threadIdx.x & 31) == 0) s_red[threadIdx.x >> 5] = loss;
    __syncthreads();
    if (threadIdx.x < (THREADS/32)) {
        float v = s_red[threadIdx.x];
        #pragma unroll
        for (int off = (THREADS/64); off > 0; off >>= 1)
            v += __shfl_down_sync(0xffu, v, off);
        if (threadIdx.x == 0) g_partial[blockIdx.x] = v;
    }
}

// ---------------------------------------------------------------------------
// Kernel 2: final deterministic reduction of block partials -> scalar
// ---------------------------------------------------------------------------
__global__ void __launch_bounds__(RED_THREADS)
emloss_reduce(float* __restrict__ out_scalar) {
    float s = 0.f;
    for (int i = threadIdx.x; i < NBLOCKS; i += RED_THREADS)
        s += g_partial[i];
    #pragma unroll
    for (int off = 16; off > 0; off >>= 1)
        s += __shfl_down_sync(0xffffffffu, s, off);
    __shared__ float s_red[RED_THREADS/32];
    if ((threadIdx.x & 31) == 0) s_red[threadIdx.x >> 5] = s;
    __syncthreads();
    if (threadIdx.x < (RED_THREADS/32)) {
        float v = s_red[threadIdx.x];
        #pragma unroll
        for (int off = (RED_THREADS/64); off > 0; off >>= 1)
            v += __shfl_down_sync(0xffffffffu, v, off);
        if (threadIdx.x == 0)
            out_scalar[0] = -v / (float)NPIX;
    }
}

extern "C" void kernel_launch(void* const* d_in, const int* in_sizes, int n_in,
                              void* d_out, int out_size) {
    const float* logits  = (const float*)d_in[0];
    const int*   targets = (const int*)d_in[1];
    const float* cm      = (const float*)d_in[2];
    float* out = (float*)d_out;

    prep_kernel<<<1, 32>>>(cm);
    emloss_main<<<NBLOCKS, THREADS>>>(logits, targets, out);
    emloss_reduce<<<1, RED_THREADS>>>(out + (out_size - 1));
}